// round 1
// baseline (speedup 1.0000x reference)
#include <cuda_runtime.h>

#define B_  4
#define S_  2048
#define D_  512
#define H_  8
#define DH_ 64
#define BH_ (B_ * H_)

// Scratch for projected q/k/v in [B,H,S,DH] layout (16MB each; __device__ globals
// are the allowed scratch mechanism under _HX_ENFORCE).
__device__ float g_q[B_ * H_ * S_ * DH_];
__device__ float g_k[B_ * H_ * S_ * DH_];
__device__ float g_v[B_ * H_ * S_ * DH_];

// ---------------------------------------------------------------------------
// Kernel A: fused QKV projection.
//   For each (w in {q,k,v}, head h): OUT[bh][s][dh] = sum_d x[b,s,d] * W[h,d,dh]
//   Block computes a 64(M) x 64(N=DH) tile with K=512, BK=16.
//   256 threads, 4x4 micro-tile per thread.
//   Xs stored k-major (transposed) so the inner loop reads broadcast float4s.
// ---------------------------------------------------------------------------
__global__ __launch_bounds__(256) void qkv_kernel(
    const float* __restrict__ x,
    const float* __restrict__ Wq,
    const float* __restrict__ Wk,
    const float* __restrict__ Wv)
{
    __shared__ float Xs[16][68];   // [k][row], pad 68 keeps 16B alignment + bank spread
    __shared__ float Ws[16][64];   // [k][col]

    const int t  = threadIdx.x;
    const int tx = t & 15;
    const int ty = t >> 4;
    const int m0 = blockIdx.x * 64;          // global row tile (over B*S = 8192)
    const int wh = blockIdx.y;               // 0..23 : (which weight)*8 + head
    const int w  = wh >> 3;
    const int h  = wh & 7;

    const float* W   = (w == 0 ? Wq : (w == 1 ? Wk : Wv)) + h * D_ * DH_;
    float*       out = (w == 0 ? g_q : (w == 1 ? g_k : g_v));

    const int xr = t >> 2;                   // 0..63  (row within M tile)
    const int xc = (t & 3) << 2;             // 0,4,8,12 (k offset)
    const int wr = t >> 4;                   // 0..15  (k row)
    const int wc = (t & 15) << 2;            // 0..60  (col)

    float acc[4][4] = {};

    for (int k0 = 0; k0 < D_; k0 += 16) {
        float4 xv = *reinterpret_cast<const float4*>(&x[(m0 + xr) * D_ + k0 + xc]);
        Xs[xc + 0][xr] = xv.x;
        Xs[xc + 1][xr] = xv.y;
        Xs[xc + 2][xr] = xv.z;
        Xs[xc + 3][xr] = xv.w;
        *reinterpret_cast<float4*>(&Ws[wr][wc]) =
            *reinterpret_cast<const float4*>(&W[(k0 + wr) * DH_ + wc]);
        __syncthreads();

        #pragma unroll
        for (int kk = 0; kk < 16; kk++) {
            float4 a4 = *reinterpret_cast<const float4*>(&Xs[kk][ty << 2]);
            float4 b4 = *reinterpret_cast<const float4*>(&Ws[kk][tx << 2]);
            float a[4] = {a4.x, a4.y, a4.z, a4.w};
            float b[4] = {b4.x, b4.y, b4.z, b4.w};
            #pragma unroll
            for (int i = 0; i < 4; i++)
                #pragma unroll
                for (int j = 0; j < 4; j++)
                    acc[i][j] = fmaf(a[i], b[j], acc[i][j]);
        }
        __syncthreads();
    }

    #pragma unroll
    for (int i = 0; i < 4; i++) {
        int m = m0 + (ty << 2) + i;
        int b = m >> 11;              // / S_
        int s = m & (S_ - 1);
        float4 o4 = make_float4(acc[i][0], acc[i][1], acc[i][2], acc[i][3]);
        *reinterpret_cast<float4*>(
            &out[(((b * H_ + h) * S_) + s) * DH_ + (tx << 2)]) = o4;
    }
}

// ---------------------------------------------------------------------------
// Kernel B: flash attention (fp32, online softmax).
//   grid = (S/64 query tiles, B*H). Block: 256 threads, 64 queries.
//   Loops over 32 key tiles of 64. Q/K stored d-major (transposed) in smem so
//   QK^T inner loop is broadcast float4 + conflict-free float4.
//   P stored kj-major so PV inner loop is the same shape.
// ---------------------------------------------------------------------------
#define TPAD 68
#define ATTN_SMEM (4 * 64 * TPAD * 4)

__global__ __launch_bounds__(256) void attn_kernel(float* __restrict__ out)
{
    extern __shared__ float sm[];
    float* Qst = sm;                 // [d][qi]  stride TPAD
    float* Kst = sm + 64 * TPAD;     // [d][kj]
    float* Vs  = sm + 2 * 64 * TPAD; // [kj][d]
    float* Pst = sm + 3 * 64 * TPAD; // [kj][qi]

    const int t  = threadIdx.x;
    const int tx = t & 15;           // -> 4 cols (kj for S, d for O)
    const int ty = t >> 4;           // -> 4 rows (qi)
    const int q0 = blockIdx.x * 64;
    const int bh = blockIdx.y;

    const float* qp = g_q + bh * S_ * DH_;
    const float* kp = g_k + bh * S_ * DH_;
    const float* vp = g_v + bh * S_ * DH_;

    const int lr = t >> 2;           // 0..63
    const int lc = (t & 3) << 2;     // 0,4,8,12

    // Load Q tile transposed: Qst[d][qi]
    #pragma unroll
    for (int it = 0; it < 4; it++) {
        int d0 = lc + it * 16;
        float4 qv = *reinterpret_cast<const float4*>(&qp[(q0 + lr) * DH_ + d0]);
        Qst[(d0 + 0) * TPAD + lr] = qv.x;
        Qst[(d0 + 1) * TPAD + lr] = qv.y;
        Qst[(d0 + 2) * TPAD + lr] = qv.z;
        Qst[(d0 + 3) * TPAD + lr] = qv.w;
    }

    float o[4][4] = {};
    float m_run[4], l_run[4];
    #pragma unroll
    for (int i = 0; i < 4; i++) { m_run[i] = -1e30f; l_run[i] = 0.0f; }
    const float scale = 0.125f;      // DH^-0.5

    for (int kt = 0; kt < S_ / 64; kt++) {
        __syncthreads();             // protect Kst/Vs from previous iteration's readers
        const int s0 = kt * 64;
        #pragma unroll
        for (int it = 0; it < 4; it++) {
            int d0 = lc + it * 16;
            float4 kv = *reinterpret_cast<const float4*>(&kp[(s0 + lr) * DH_ + d0]);
            Kst[(d0 + 0) * TPAD + lr] = kv.x;
            Kst[(d0 + 1) * TPAD + lr] = kv.y;
            Kst[(d0 + 2) * TPAD + lr] = kv.z;
            Kst[(d0 + 3) * TPAD + lr] = kv.w;
            *reinterpret_cast<float4*>(&Vs[lr * TPAD + d0]) =
                *reinterpret_cast<const float4*>(&vp[(s0 + lr) * DH_ + d0]);
        }
        __syncthreads();

        // S = Q @ K^T  (4x4 per thread)
        float sv[4][4] = {};
        #pragma unroll 16
        for (int d = 0; d < 64; d++) {
            float4 a4 = *reinterpret_cast<const float4*>(&Qst[d * TPAD + (ty << 2)]);
            float4 b4 = *reinterpret_cast<const float4*>(&Kst[d * TPAD + (tx << 2)]);
            float a[4] = {a4.x, a4.y, a4.z, a4.w};
            float b[4] = {b4.x, b4.y, b4.z, b4.w};
            #pragma unroll
            for (int i = 0; i < 4; i++)
                #pragma unroll
                for (int j = 0; j < 4; j++)
                    sv[i][j] = fmaf(a[i], b[j], sv[i][j]);
        }

        // Online softmax (row groups = 16 lanes within a warp half)
        float m_new[4], alpha[4];
        #pragma unroll
        for (int i = 0; i < 4; i++) {
            float rm = sv[i][0];
            #pragma unroll
            for (int j = 1; j < 4; j++) rm = fmaxf(rm, sv[i][j]);
            #pragma unroll
            for (int off = 1; off < 16; off <<= 1)
                rm = fmaxf(rm, __shfl_xor_sync(0xffffffffu, rm, off));
            m_new[i] = fmaxf(m_run[i], rm * scale);
            alpha[i] = __expf(m_run[i] - m_new[i]);
        }
        #pragma unroll
        for (int i = 0; i < 4; i++) {
            float rs = 0.0f;
            #pragma unroll
            for (int j = 0; j < 4; j++) {
                float p = __expf(fmaf(sv[i][j], scale, -m_new[i]));
                Pst[((tx << 2) + j) * TPAD + (ty << 2) + i] = p;
                rs += p;
            }
            #pragma unroll
            for (int off = 1; off < 16; off <<= 1)
                rs += __shfl_xor_sync(0xffffffffu, rs, off);
            l_run[i] = l_run[i] * alpha[i] + rs;
            m_run[i] = m_new[i];
            #pragma unroll
            for (int j = 0; j < 4; j++) o[i][j] *= alpha[i];
        }
        __syncthreads();

        // O += P @ V
        #pragma unroll 16
        for (int kj = 0; kj < 64; kj++) {
            float4 a4 = *reinterpret_cast<const float4*>(&Pst[kj * TPAD + (ty << 2)]);
            float4 b4 = *reinterpret_cast<const float4*>(&Vs[kj * TPAD + (tx << 2)]);
            float a[4] = {a4.x, a4.y, a4.z, a4.w};
            float b[4] = {b4.x, b4.y, b4.z, b4.w};
            #pragma unroll
            for (int i = 0; i < 4; i++)
                #pragma unroll
                for (int j = 0; j < 4; j++)
                    o[i][j] = fmaf(a[i], b[j], o[i][j]);
        }
    }

    // Epilogue: normalize and write [B,S,H*DH]
    const int b = bh >> 3;
    const int h = bh & 7;
    #pragma unroll
    for (int i = 0; i < 4; i++) {
        float inv = 1.0f / l_run[i];
        int s = q0 + (ty << 2) + i;
        float4 o4 = make_float4(o[i][0] * inv, o[i][1] * inv,
                                o[i][2] * inv, o[i][3] * inv);
        *reinterpret_cast<float4*>(
            &out[((b * S_ + s) * H_ + h) * DH_ + (tx << 2)]) = o4;
    }
}

extern "C" void kernel_launch(void* const* d_in, const int* in_sizes, int n_in,
                              void* d_out, int out_size)
{
    const float* x  = (const float*)d_in[0];
    const float* Wq = (const float*)d_in[1];
    const float* Wk = (const float*)d_in[2];
    const float* Wv = (const float*)d_in[3];
    float* out = (float*)d_out;

    cudaFuncSetAttribute(attn_kernel,
                         cudaFuncAttributeMaxDynamicSharedMemorySize, ATTN_SMEM);

    qkv_kernel<<<dim3((B_ * S_) / 64, 3 * H_), 256>>>(x, Wq, Wk, Wv);
    attn_kernel<<<dim3(S_ / 64, BH_), 256, ATTN_SMEM>>>(out);
}